// round 3
// baseline (speedup 1.0000x reference)
#include <cuda_runtime.h>

#define B_    8
#define C_    1024
#define T_    1500
#define M_    (B_*T_)
#define KC_   8192
#define D_    256
#define H_    512
#define NQ_   4
#define BINS_ 1024
#define LRELU_SLOPE 0.01f
#define EPS_  1e-8f

__device__ __align__(16) float g_x   [M_*C_];
__device__ __align__(16) float g_lin [M_*C_];
__device__ __align__(16) float g_raw [M_*C_];
__device__ __align__(16) float g_obt [M_*C_];
__device__ __align__(16) float g_h0  [M_*H_];
__device__ __align__(16) float g_h1  [M_*H_];
__device__ __align__(16) float g_spk [M_*D_];
__device__ __align__(16) float g_nrm [M_*D_];
__device__ __align__(16) float g_sen [M_*D_];   // spk_enc_norm (kept)
__device__ __align__(16) float g_res [M_*D_];
__device__ __align__(16) float g_qs  [M_*D_];
__device__ __align__(16) float g_den [M_*D_];
__device__ float g_cnorm[KC_];
__device__ float g_bnorm[NQ_*BINS_];
__device__ float g_E[M_];                       // row sumsq (shared for ling/rvq)
__device__ unsigned long long g_mk[M_];

__device__ __forceinline__ unsigned int f2key(float f) {
    unsigned int u = __float_as_uint(f);
    return (u & 0x80000000u) ? ~u : (u | 0x80000000u);
}

// ---- row sum-of-squares emulating LLVM VF=4 x IC=4 vectorized reduce ------
// p_l = sum_j fma(x[16j+l]^2)  (l = 0..15, j ascending)
// c_l = fl( fl(p_l + p_{l+4}) + fl(p_{l+8} + p_{l+12}) ), l = 0..3
// s   = fl( fl(c0+c1) + fl(c2+c3) )
__global__ void row_sumsq16(const float* __restrict__ rows, float* __restrict__ out,
                            int R, int L) {
    int r = blockIdx.x * blockDim.x + threadIdx.x;
    if (r >= R) return;
    const float* p = rows + (size_t)r * L;
    float pl[16];
    #pragma unroll
    for (int l = 0; l < 16; l++) pl[l] = 0.0f;
    for (int j = 0; j < L; j += 16) {
        #pragma unroll
        for (int l = 0; l < 16; l++) {
            float v = __ldg(p + j + l);
            pl[l] = __fmaf_rn(v, v, pl[l]);
        }
    }
    float c[4];
    #pragma unroll
    for (int l = 0; l < 4; l++)
        c[l] = __fadd_rn(__fadd_rn(pl[l], pl[l + 4]),
                         __fadd_rn(pl[l + 8], pl[l + 12]));
    out[r] = __fadd_rn(__fadd_rn(c[0], c[1]), __fadd_rn(c[2], c[3]));
}

__global__ void reset_mk() {
    int i = blockIdx.x * blockDim.x + threadIdx.x;
    if (i < M_) g_mk[i] = ~0ull;
}

__global__ void transpose_in(const float* __restrict__ f, float* __restrict__ x) {
    __shared__ float tile[32][33];
    int b = blockIdx.z, t0 = blockIdx.x * 32, c0 = blockIdx.y * 32;
    int tx = threadIdx.x, ty = threadIdx.y;
    #pragma unroll
    for (int i = 0; i < 32; i += 8) {
        int cc = c0 + ty + i, t = t0 + tx;
        if (t < T_ && cc < C_) tile[ty + i][tx] = f[((size_t)b * C_ + cc) * T_ + t];
    }
    __syncthreads();
    #pragma unroll
    for (int i = 0; i < 32; i += 8) {
        int tt = t0 + ty + i, cc = c0 + tx;
        if (tt < T_ && cc < C_) x[((size_t)b * T_ + tt) * C_ + cc] = tile[tx][ty + i];
    }
}

__global__ void transpose_out(const float* __restrict__ x, float* __restrict__ f) {
    __shared__ float tile[32][33];
    int b = blockIdx.z, t0 = blockIdx.x * 32, c0 = blockIdx.y * 32;
    int tx = threadIdx.x, ty = threadIdx.y;
    #pragma unroll
    for (int i = 0; i < 32; i += 8) {
        int tt = t0 + ty + i, cc = c0 + tx;
        if (tt < T_ && cc < C_) tile[ty + i][tx] = x[((size_t)b * T_ + tt) * C_ + cc];
    }
    __syncthreads();
    #pragma unroll
    for (int i = 0; i < 32; i += 8) {
        int cc = c0 + ty + i, t = t0 + tx;
        if (t < T_ && cc < C_) f[((size_t)b * C_ + cc) * T_ + t] = tile[tx][ty + i];
    }
}

// ---- GEMM + argmin with reference semantics:
// F = ascending-k single-rounded fma; dist = fl( fl(E - 2F) + G ); first-min idx.
__global__ __launch_bounds__(256)
void gemm_argmin(const float* __restrict__ A, const float* __restrict__ Bm,
                 const float* __restrict__ G, const float* __restrict__ E,
                 unsigned long long* __restrict__ mk, int M, int N, int K) {
    __shared__ float As[8][128];
    __shared__ float Bs[8][128];
    int tid = threadIdx.x;
    int m0 = blockIdx.y * 128, n0 = blockIdx.x * 128;
    int rg = tid >> 4, cg = tid & 15;
    int lr = tid >> 1, lk = (tid & 1) * 4;
    float acc[8][8] = {};
    for (int k0 = 0; k0 < K; k0 += 8) {
        float4 av = make_float4(0.f, 0.f, 0.f, 0.f);
        int gm = m0 + lr;
        if (gm < M) av = *(const float4*)(A + (size_t)gm * K + k0 + lk);
        As[lk][lr] = av.x; As[lk+1][lr] = av.y; As[lk+2][lr] = av.z; As[lk+3][lr] = av.w;
        float4 bv = *(const float4*)(Bm + (size_t)(n0 + lr) * K + k0 + lk);
        Bs[lk][lr] = bv.x; Bs[lk+1][lr] = bv.y; Bs[lk+2][lr] = bv.z; Bs[lk+3][lr] = bv.w;
        __syncthreads();
        #pragma unroll
        for (int kk = 0; kk < 8; kk++) {
            float a[8], b[8];
            *(float4*)&a[0] = *(const float4*)&As[kk][rg * 8];
            *(float4*)&a[4] = *(const float4*)&As[kk][rg * 8 + 4];
            *(float4*)&b[0] = *(const float4*)&Bs[kk][cg * 8];
            *(float4*)&b[4] = *(const float4*)&Bs[kk][cg * 8 + 4];
            #pragma unroll
            for (int i = 0; i < 8; i++)
                #pragma unroll
                for (int j = 0; j < 8; j++)
                    acc[i][j] = __fmaf_rn(a[i], b[j], acc[i][j]);
        }
        __syncthreads();
    }
    float gv[8];
    #pragma unroll
    for (int j = 0; j < 8; j++) gv[j] = G[n0 + cg * 8 + j];
    float ev[8];
    #pragma unroll
    for (int i = 0; i < 8; i++) {
        int gm = m0 + rg * 8 + i;
        ev[i] = (gm < M) ? E[gm] : 0.0f;
    }
    unsigned long long best[8];
    #pragma unroll
    for (int i = 0; i < 8; i++) {
        unsigned long long bb = ~0ull;
        #pragma unroll
        for (int j = 0; j < 8; j++) {
            float t1 = __fmul_rn(2.0f, acc[i][j]);   // exact
            float t2 = __fadd_rn(ev[i], -t1);        // fl(E - 2F)
            float s  = __fadd_rn(t2, gv[j]);         // fl(.. + G)
            unsigned long long pk =
                ((unsigned long long)f2key(s) << 32) | (unsigned)(n0 + cg * 8 + j);
            bb = (pk < bb) ? pk : bb;
        }
        best[i] = bb;
    }
    #pragma unroll
    for (int off = 1; off < 16; off <<= 1) {
        #pragma unroll
        for (int i = 0; i < 8; i++) {
            unsigned long long o = __shfl_xor_sync(0xffffffffu, best[i], off);
            best[i] = (o < best[i]) ? o : best[i];
        }
    }
    if (cg == 0) {
        #pragma unroll
        for (int i = 0; i < 8; i++) {
            int gm = m0 + rg * 8 + i;
            if (gm < M) atomicMin(&mk[gm], best[i]);
        }
    }
}

// ---- GEMM + bias + act (+ residual add). All roundings explicit. ----------
template <int ACT, bool ADD>
__global__ __launch_bounds__(256)
void gemm_bias_act(const float* __restrict__ A, const float* __restrict__ W,
                   const float* __restrict__ bias, const float* __restrict__ addin,
                   float* __restrict__ Cp, int M, int N, int K) {
    __shared__ float As[8][128];
    __shared__ float Ws[8][128];
    int tid = threadIdx.x;
    int m0 = blockIdx.y * 128, n0 = blockIdx.x * 128;
    int rg = tid >> 4, cg = tid & 15;
    int lr = tid >> 1, lk = (tid & 1) * 4;
    int wk = tid >> 5, wn = (tid & 31) * 4;
    float acc[8][8] = {};
    for (int k0 = 0; k0 < K; k0 += 8) {
        float4 av = make_float4(0.f, 0.f, 0.f, 0.f);
        int gm = m0 + lr;
        if (gm < M) av = *(const float4*)(A + (size_t)gm * K + k0 + lk);
        As[lk][lr] = av.x; As[lk+1][lr] = av.y; As[lk+2][lr] = av.z; As[lk+3][lr] = av.w;
        *(float4*)&Ws[wk][wn] = *(const float4*)(W + (size_t)(k0 + wk) * N + n0 + wn);
        __syncthreads();
        #pragma unroll
        for (int kk = 0; kk < 8; kk++) {
            float a[8], b[8];
            *(float4*)&a[0] = *(const float4*)&As[kk][rg * 8];
            *(float4*)&a[4] = *(const float4*)&As[kk][rg * 8 + 4];
            *(float4*)&b[0] = *(const float4*)&Ws[kk][cg * 8];
            *(float4*)&b[4] = *(const float4*)&Ws[kk][cg * 8 + 4];
            #pragma unroll
            for (int i = 0; i < 8; i++)
                #pragma unroll
                for (int j = 0; j < 8; j++)
                    acc[i][j] = __fmaf_rn(a[i], b[j], acc[i][j]);
        }
        __syncthreads();
    }
    float bv[8];
    #pragma unroll
    for (int j = 0; j < 8; j++) bv[j] = bias[n0 + cg * 8 + j];
    #pragma unroll
    for (int i = 0; i < 8; i++) {
        int gm = m0 + rg * 8 + i;
        if (gm < M) {
            size_t base = (size_t)gm * N + n0 + cg * 8;
            #pragma unroll
            for (int j = 0; j < 8; j += 4) {
                float v[4];
                #pragma unroll
                for (int q = 0; q < 4; q++) {
                    float t = __fadd_rn(acc[i][j + q], bv[j + q]);
                    if (ACT == 1) t = (t >= 0.f) ? t : __fmul_rn(LRELU_SLOPE, t);
                    if (ACT == 2) t = fmaxf(t, 0.f);
                    v[q] = t;
                }
                if (ADD) {
                    float4 ad = *(const float4*)(addin + base + j);
                    v[0] = __fadd_rn(v[0], ad.x); v[1] = __fadd_rn(v[1], ad.y);
                    v[2] = __fadd_rn(v[2], ad.z); v[3] = __fadd_rn(v[3], ad.w);
                }
                *(float4*)(Cp + base + j) = make_float4(v[0], v[1], v[2], v[3]);
            }
        }
    }
}

__global__ void gather_sub(const float* __restrict__ cent) {
    int i = blockIdx.x * blockDim.x + threadIdx.x;
    if (i >= M_ * (C_ / 4)) return;
    int m = i / (C_ / 4), j = i % (C_ / 4);
    int idx = (int)(g_mk[m] & 0xffffffffu);
    float4 cv = *(const float4*)(cent + (size_t)idx * C_ + j * 4);
    float4 xv = *(const float4*)(g_x + (size_t)m * C_ + j * 4);
    *(float4*)(g_lin + (size_t)m * C_ + j * 4) = cv;
    float4 rv = make_float4(__fadd_rn(xv.x, -cv.x), __fadd_rn(xv.y, -cv.y),
                            __fadd_rn(xv.z, -cv.z), __fadd_rn(xv.w, -cv.w));
    *(float4*)(g_raw + (size_t)m * C_ + j * 4) = rv;
}

// sen = spk / fl(nrm + eps); res = sen; qs = 0
__global__ void norm_div_init() {
    int i = blockIdx.x * blockDim.x + threadIdx.x;
    if (i >= M_ * D_) return;
    float se = g_spk[i], nv = g_nrm[i];
    float r = __fdiv_rn(se, __fadd_rn(nv, EPS_));
    g_sen[i] = r;
    g_res[i] = r;
    g_qs[i] = 0.f;
}

__global__ void rvq_update(const float* __restrict__ cb, int stage) {
    int i = blockIdx.x * blockDim.x + threadIdx.x;
    if (i >= M_ * (D_ / 4)) return;
    int m = i / (D_ / 4), j = i % (D_ / 4);
    int idx = (int)(g_mk[m] & 0xffffffffu);
    float4 q = *(const float4*)(cb + ((size_t)stage * BINS_ + idx) * D_ + j * 4);
    float4 qs = ((const float4*)g_qs)[i];
    float4 rs = ((const float4*)g_res)[i];
    ((float4*)g_qs)[i] = make_float4(__fadd_rn(qs.x, q.x), __fadd_rn(qs.y, q.y),
                                     __fadd_rn(qs.z, q.z), __fadd_rn(qs.w, q.w));
    ((float4*)g_res)[i] = make_float4(__fadd_rn(rs.x, -q.x), __fadd_rn(rs.y, -q.y),
                                      __fadd_rn(rs.z, -q.z), __fadd_rn(rs.w, -q.w));
}

// quantized = fl(sen + fl(qs - sen));  den = fl(quantized * nrm)
__global__ void denorm_mul() {
    int i = blockIdx.x * blockDim.x + threadIdx.x;
    if (i >= M_ * D_) return;
    float sen = g_sen[i], qs = g_qs[i], nv = g_nrm[i];
    float quant = __fadd_rn(sen, __fadd_rn(qs, -sen));
    g_den[i] = __fmul_rn(quant, nv);
}

static float* symf(const void* sym) {
    void* p = nullptr;
    cudaGetSymbolAddress(&p, sym);
    return (float*)p;
}

extern "C" void kernel_launch(void* const* d_in, const int* in_sizes, int n_in,
                              void* d_out, int out_size) {
    const float* feature  = (const float*)d_in[0];
    const float* centroid = (const float*)d_in[1];
    const float* enc_w0 = (const float*)d_in[2];  const float* enc_b0 = (const float*)d_in[3];
    const float* enc_w1 = (const float*)d_in[4];  const float* enc_b1 = (const float*)d_in[5];
    const float* enc_w2 = (const float*)d_in[6];  const float* enc_b2 = (const float*)d_in[7];
    const float* dec_w0 = (const float*)d_in[8];  const float* dec_b0 = (const float*)d_in[9];
    const float* dec_w1 = (const float*)d_in[10]; const float* dec_b1 = (const float*)d_in[11];
    const float* dec_w2 = (const float*)d_in[12]; const float* dec_b2 = (const float*)d_in[13];
    const float* nrm_w0 = (const float*)d_in[14]; const float* nrm_b0 = (const float*)d_in[15];
    const float* nrm_w1 = (const float*)d_in[16]; const float* nrm_b1 = (const float*)d_in[17];
    const float* nrm_w2 = (const float*)d_in[18]; const float* nrm_b2 = (const float*)d_in[19];
    const float* codebooks = (const float*)d_in[20];
    float* out = (float*)d_out;

    float* px   = symf(g_x);    float* plin = symf(g_lin);
    float* praw = symf(g_raw);  float* pobt = symf(g_obt);
    float* ph0  = symf(g_h0);   float* ph1  = symf(g_h1);
    float* pspk = symf(g_spk);  float* pnrm = symf(g_nrm);
    float* pres = symf(g_res);  float* pden = symf(g_den);
    float* pcn  = symf(g_cnorm); float* pbn = symf(g_bnorm);
    float* pE   = symf(g_E);
    void* pmkv = nullptr; cudaGetSymbolAddress(&pmkv, g_mk);
    unsigned long long* pmk = (unsigned long long*)pmkv;

    dim3 tb(32, 8);
    dim3 tg((T_ + 31) / 32, C_ / 32, B_);
    transpose_in<<<tg, tb>>>(feature, px);

    // norms with reference reduce-order emulation
    row_sumsq16<<<(KC_ + 127) / 128, 128>>>(centroid, pcn, KC_, C_);
    row_sumsq16<<<(NQ_ * BINS_ + 127) / 128, 128>>>(codebooks, pbn, NQ_ * BINS_, D_);
    row_sumsq16<<<(M_ + 127) / 128, 128>>>(px, pE, M_, C_);

    reset_mk<<<(M_ + 255) / 256, 256>>>();
    {
        dim3 g(KC_ / 128, (M_ + 127) / 128);
        gemm_argmin<<<g, 256>>>(px, centroid, pcn, pE, pmk, M_, KC_, C_);
    }
    gather_sub<<<(M_ * (C_ / 4) + 255) / 256, 256>>>(centroid);

    dim3 gH(H_ / 128, (M_ + 127) / 128);
    dim3 gD(D_ / 128, (M_ + 127) / 128);
    dim3 gC(C_ / 128, (M_ + 127) / 128);

    gemm_bias_act<1, false><<<gH, 256>>>(praw, enc_w0, enc_b0, nullptr, ph0, M_, H_, C_);
    gemm_bias_act<1, false><<<gH, 256>>>(ph0, enc_w1, enc_b1, nullptr, ph1, M_, H_, H_);
    gemm_bias_act<0, false><<<gD, 256>>>(ph1, enc_w2, enc_b2, nullptr, pspk, M_, D_, H_);
    gemm_bias_act<2, false><<<gH, 256>>>(plin, nrm_w0, nrm_b0, nullptr, ph0, M_, H_, C_);
    gemm_bias_act<2, false><<<gH, 256>>>(ph0, nrm_w1, nrm_b1, nullptr, ph1, M_, H_, H_);
    gemm_bias_act<2, false><<<gD, 256>>>(ph1, nrm_w2, nrm_b2, nullptr, pnrm, M_, D_, H_);

    norm_div_init<<<(M_ * D_ + 255) / 256, 256>>>();

    for (int s = 0; s < NQ_; s++) {
        row_sumsq16<<<(M_ + 127) / 128, 128>>>(pres, pE, M_, D_);
        reset_mk<<<(M_ + 255) / 256, 256>>>();
        dim3 g(BINS_ / 128, (M_ + 127) / 128);
        gemm_argmin<<<g, 256>>>(pres, codebooks + (size_t)s * BINS_ * D_,
                                pbn + s * BINS_, pE, pmk, M_, BINS_, D_);
        rvq_update<<<(M_ * (D_ / 4) + 255) / 256, 256>>>(codebooks, s);
    }

    denorm_mul<<<(M_ * D_ + 255) / 256, 256>>>();

    gemm_bias_act<1, false><<<gH, 256>>>(pden, dec_w0, dec_b0, nullptr, ph0, M_, H_, D_);
    gemm_bias_act<1, false><<<gH, 256>>>(ph0, dec_w1, dec_b1, nullptr, ph1, M_, H_, H_);
    gemm_bias_act<0, true><<<gC, 256>>>(ph1, dec_w2, dec_b2, plin, pobt, M_, C_, H_);

    transpose_out<<<tg, tb>>>(pobt, out);
}